// round 1
// baseline (speedup 1.0000x reference)
#include <cuda_runtime.h>
#include <math.h>

#define BB 4
#define CC 7
#define HH 512
#define WW 1024
#define HW (HH*WW)            // 524288
#define NID 7
#define NTASK (BB*NID)        // 28
#define NBINS 131072
#define HALFBINS 65536

// ---- persistent scratch (allocation-free rule: __device__ globals) ----
__device__ float    g_embx[BB*HW];
__device__ float    g_emby[BB*HW];
__device__ float    g_seed[BB*HW];
__device__ unsigned g_nt[NTASK*NBINS];
__device__ unsigned g_nf[NTASK*NBINS];
__device__ float    g_stat[NTASK*7];    // cnt, sum_xm, sum_ym, s0, s1, s0^2, s1^2
__device__ float    g_batch[BB*3];      // cls_sum, valid_cnt, seed_bg
__device__ float    g_task[NTASK*8];    // cx, cy, sex, sey, varl, present
__device__ float    g_seedfg[NTASK];
__device__ float    g_instl[NTASK];

// ---------------- zero accumulators ----------------
__global__ __launch_bounds__(256) void zeroK() {
    int i = blockIdx.x*blockDim.x + threadIdx.x;
    int stride = gridDim.x*blockDim.x;
    for (int j = i; j < NTASK*NBINS; j += stride) { g_nt[j]=0u; g_nf[j]=0u; }
    if (blockIdx.x == 0) {
        for (int j = threadIdx.x; j < NTASK*7; j += blockDim.x) g_stat[j]=0.f;
        if (threadIdx.x < BB*3)   g_batch[threadIdx.x]=0.f;
        if (threadIdx.x < NTASK)  g_seedfg[threadIdx.x]=0.f;
    }
}

// ---------------- stage A: per-pixel transforms + per-(b,id) stats ----------------
__global__ __launch_bounds__(256) void stageA(const float* __restrict__ pred,
                                              const int*  __restrict__ inst,
                                              const int*  __restrict__ lab) {
    __shared__ float s_acc[52];   // 7 ids * 7 stats + cls, vcnt, seedbg
    int b = blockIdx.y;
    for (int i = threadIdx.x; i < 52; i += 256) s_acc[i] = 0.f;
    __syncthreads();

    const float* pb = pred + b*(CC*HW);
    int base = blockIdx.x*1024;
    float cls = 0.f, vc = 0.f, sbg = 0.f;

    #pragma unroll
    for (int k = 0; k < 4; k++) {
        int pix = base + k*256 + threadIdx.x;
        float p0 = pb[pix],      p1 = pb[HW+pix],   p2 = pb[2*HW+pix];
        float p3 = pb[3*HW+pix], p4 = pb[4*HW+pix];
        float p5 = pb[5*HW+pix], p6 = pb[6*HW+pix];
        int iv = inst[b*HW+pix];
        int lv = lab [b*HW+pix];
        int w = pix & (WW-1);
        int h = pix >> 10;

        float xw = (2.0f/2047.0f)*(float)w;   // xm = linspace(0,2,2048)[:W]
        float yh = (1.0f/1023.0f)*(float)h;   // ym = linspace(0,1,1024)[:H]
        float ex = tanhf(p0) + xw;
        float ey = tanhf(p1) + yh;
        float sd = 1.0f/(1.0f + expf(-p4));
        g_embx[b*HW+pix] = ex;
        g_emby[b*HW+pix] = ey;
        g_seed[b*HW+pix] = sd;

        if (lv < 2) {  // focal loss, 2-class log-softmax over (p5,p6)
            float m   = fmaxf(p5, p6);
            float lse = m + logf(expf(p5-m) + expf(p6-m));
            float logpt = ((lv == 0) ? p5 : p6) - lse;
            float pt  = expf(logpt);
            float om  = 1.0f - pt;
            cls -= om*om*logpt;
            vc  += 1.0f;
        }
        if (lv == 0) sbg += sd*sd;

        if (iv >= 1) {
            float* a = &s_acc[(iv-1)*7];
            atomicAdd(a+0, 1.0f);
            atomicAdd(a+1, xw);
            atomicAdd(a+2, yh);
            atomicAdd(a+3, p2);
            atomicAdd(a+4, p3);
            atomicAdd(a+5, p2*p2);
            atomicAdd(a+6, p3*p3);
        }
    }
    atomicAdd(&s_acc[49], cls);
    atomicAdd(&s_acc[50], vc);
    atomicAdd(&s_acc[51], sbg);
    __syncthreads();
    if      (threadIdx.x < 49) atomicAdd(&g_stat[b*49 + threadIdx.x], s_acc[threadIdx.x]);
    else if (threadIdx.x < 52) atomicAdd(&g_batch[b*3 + threadIdx.x - 49], s_acc[threadIdx.x]);
}

// ---------------- stage B: per-task derived params ----------------
__global__ void stageB() {
    int t = threadIdx.x;
    if (t >= NTASK) return;
    const float* s = &g_stat[t*7];
    float cnt  = s[0];
    float pres = (cnt > 0.f) ? 1.f : 0.f;
    float cf   = fmaxf(cnt, 1.f);
    float cx = s[1]/cf, cy = s[2]/cf;
    float m0 = s[3]/cf, m1 = s[4]/cf;
    float varl = (s[5] - cnt*m0*m0 + s[6] - cnt*m1*m1) / (2.f*cf);  // N_SIGMA=2
    g_task[t*8+0] = cx;
    g_task[t*8+1] = cy;
    g_task[t*8+2] = expf(10.f*m0);
    g_task[t*8+3] = expf(10.f*m1);
    g_task[t*8+4] = varl;
    g_task[t*8+5] = pres;
}

// ---------------- stage C: dist map -> error histograms + seed_fg ----------------
__global__ __launch_bounds__(256) void stageC(const int* __restrict__ inst) {
    int t = blockIdx.y;
    if (g_task[t*8+5] == 0.f) return;   // absent id: contributes nothing
    int b  = t / NID;
    int id = t % NID + 1;
    float cx  = g_task[t*8+0], cy  = g_task[t*8+1];
    float sex = g_task[t*8+2], sey = g_task[t*8+3];
    unsigned* nt = &g_nt[t*NBINS];
    unsigned* nf = &g_nf[t*NBINS];

    int base = blockIdx.x*1024;
    int lane = threadIdx.x & 31;
    float sfg = 0.f;

    #pragma unroll
    for (int k = 0; k < 4; k++) {
        int pix = base + k*256 + threadIdx.x;
        int o = b*HW + pix;
        float ex = g_embx[o], ey = g_emby[o], sd = g_seed[o];
        int fg = (inst[o] == id);
        float dx = ex - cx, dy = ey - cy;
        float d  = expf(-(dx*dx*sex + dy*dy*sey));      // in (0,1]
        float e  = fg ? 2.f*(1.f - d) : 2.f*d;          // hinge error, >= 0
        int bin = (int)(e * (float)HALFBINS);
        bin = min(bin, NBINS-1);

        // warp-aggregated histogram atomics
        unsigned same = __match_any_sync(0xffffffffu, bin);
        if (lane == __ffs(same)-1) atomicAdd(&nt[bin], (unsigned)__popc(same));
        unsigned fgm = __ballot_sync(0xffffffffu, fg);
        if (fg) {
            unsigned sf = same & fgm;
            if (lane == __ffs(sf)-1) atomicAdd(&nf[bin], (unsigned)__popc(sf));
            float df = sd - d;
            sfg += df*df;
        }
    }
    // block-reduce seed_fg
    #pragma unroll
    for (int o = 16; o; o >>= 1) sfg += __shfl_down_sync(0xffffffffu, sfg, o);
    __shared__ float sred[8];
    if (lane == 0) sred[threadIdx.x >> 5] = sfg;
    __syncthreads();
    if (threadIdx.x == 0) {
        float s = 0.f;
        #pragma unroll
        for (int i = 0; i < 8; i++) s += sred[i];
        atomicAdd(&g_seedfg[t], s);
    }
}

// ---------------- stage D: Lovász via descending-bin scan ----------------
__global__ __launch_bounds__(1024) void stageD() {
    int t = blockIdx.x;
    if (g_task[t*8+5] == 0.f) { if (threadIdx.x == 0) g_instl[t] = 0.f; return; }
    const unsigned* nt = &g_nt[t*NBINS];
    const unsigned* nf = &g_nf[t*NBINS];
    int tid = threadIdx.x;
    const int BPT = NBINS/1024;   // 128 bins/thread, contiguous descending chunk
    int hi = NBINS-1 - tid*BPT;

    // pass 1: chunk sums
    unsigned lf = 0, lt = 0;
    #pragma unroll 8
    for (int j = 0; j < BPT; j++) { int bin = hi - j; lf += nf[bin]; lt += nt[bin]; }

    // block exclusive scan of (lf, lt)
    __shared__ unsigned sWF[32], sWT[32];
    int lane = tid & 31, warp = tid >> 5;
    unsigned incF = lf, incT = lt;
    #pragma unroll
    for (int o = 1; o < 32; o <<= 1) {
        unsigned vF = __shfl_up_sync(0xffffffffu, incF, o);
        unsigned vT = __shfl_up_sync(0xffffffffu, incT, o);
        if (lane >= o) { incF += vF; incT += vT; }
    }
    if (lane == 31) { sWF[warp] = incF; sWT[warp] = incT; }
    __syncthreads();
    if (warp == 0) {
        unsigned aF = sWF[lane], aT = sWT[lane];
        #pragma unroll
        for (int o = 1; o < 32; o <<= 1) {
            unsigned vF = __shfl_up_sync(0xffffffffu, aF, o);
            unsigned vT = __shfl_up_sync(0xffffffffu, aT, o);
            if (lane >= o) { aF += vF; aT += vT; }
        }
        sWF[lane] = aF; sWT[lane] = aT;
    }
    __syncthreads();
    unsigned exclF = (warp ? sWF[warp-1] : 0u) + incF - lf;
    unsigned exclT = (warp ? sWT[warp-1] : 0u) + incT - lt;

    double G = (double)sWF[31];   // exact fg total from histogram
    unsigned F = exclF, T = exclT;
    // jac(F,T) = 1 - (G-F)/(G+T-F); monotone 0 -> 1. Double to avoid telescoping drift.
    double jprev = 1.0 - (G - (double)F) / (G + (double)(T - F));
    double loss = 0.0;
    #pragma unroll 4
    for (int j = 0; j < BPT; j++) {
        int bin = hi - j;
        unsigned a = nf[bin], c = nt[bin];
        if (c) {
            F += a; T += c;
            double jnew = 1.0 - (G - (double)F) / (G + (double)(T - F));
            double e = ((double)bin + 0.5) * (1.0/65536.0);  // bin-center error value
            loss += e * (jnew - jprev);
            jprev = jnew;
        }
    }
    // block reduce loss
    float lossf = (float)loss;
    #pragma unroll
    for (int o = 16; o; o >>= 1) lossf += __shfl_down_sync(0xffffffffu, lossf, o);
    __shared__ float sL[32];
    if (lane == 0) sL[warp] = lossf;
    __syncthreads();
    if (warp == 0) {
        float v = sL[lane];
        #pragma unroll
        for (int o = 16; o; o >>= 1) v += __shfl_down_sync(0xffffffffu, v, o);
        if (lane == 0) g_instl[t] = v;
    }
}

// ---------------- final combine ----------------
__global__ void combineK(float* __restrict__ out) {
    if (threadIdx.x != 0) return;
    float total = 0.f;
    for (int b = 0; b < BB; b++) {
        float ps = 0.f, il = 0.f, vl = 0.f, sf = 0.f;
        for (int i = 0; i < NID; i++) {
            int t = b*NID + i;
            float p = g_task[t*8+5];
            ps += p;
            il += g_instl[t]  * p;
            vl += g_task[t*8+4] * p;
            sf += g_seedfg[t] * p;
        }
        float obj = fmaxf(ps, 1.f);
        float seed_loss = (g_batch[b*3+2] + 200.f*sf) / (float)HW;   // FG_WEIGHT=200
        float loss_b = il/obj + 10.f*(vl/obj) + seed_loss;           // W_INST=1, W_VAR=10, W_SEED=1
        float cls_b  = g_batch[b*3+0] / fmaxf(g_batch[b*3+1], 1.f);  // BALANCE=CLS_RATIO=1
        total += loss_b + cls_b;
    }
    out[0] = total * 0.25f;   // mean over B of (loss_b) + mean of (cls_b)
}

extern "C" void kernel_launch(void* const* d_in, const int* in_sizes, int n_in,
                              void* d_out, int out_size) {
    const float* pred = (const float*)d_in[0];
    const int*   inst = (const int*)  d_in[1];
    const int*   lab  = (const int*)  d_in[2];
    float* out = (float*)d_out;

    zeroK  <<<2048, 256>>>();
    stageA <<<dim3(HW/1024, BB),    256>>>(pred, inst, lab);
    stageB <<<1, 32>>>();
    stageC <<<dim3(HW/1024, NTASK), 256>>>(inst);
    stageD <<<NTASK, 1024>>>();
    combineK<<<1, 32>>>(out);
}

// round 2
// speedup vs baseline: 3.6305x; 3.6305x over previous
#include <cuda_runtime.h>
#include <math.h>

#define BB 4
#define CC 7
#define HH 512
#define WW 1024
#define HW (HH*WW)            // 524288
#define NID 7
#define NTASK (BB*NID)        // 28
#define NBINS 65536
#define BINSCALE 32768.0f
#define FULLM 0xffffffffu

// ---- persistent scratch ----
__device__ float4   g_pack[BB*HW];      // ex, ey, seed, inst(bits)
__device__ unsigned g_nb[NTASK*NBINS];  // background counts per bin
__device__ unsigned g_nf[NTASK*NBINS];  // foreground counts per bin
__device__ float    g_stat[NTASK*7];    // cnt, sum_xw, sum_yh, s0, s1, s0^2, s1^2
__device__ float    g_batch[BB*3];      // cls_sum, valid_cnt, seed_bg
__device__ float    g_task[NTASK*8];    // cx, cy, sex, sey, varl, present
__device__ float    g_seedfg[NTASK];
__device__ float    g_instl[NTASK];

// ---------------- zero accumulators ----------------
__global__ __launch_bounds__(256) void zeroK() {
    int i = blockIdx.x*blockDim.x + threadIdx.x;
    int stride = gridDim.x*blockDim.x;
    uint4* nb4 = (uint4*)g_nb;
    uint4* nf4 = (uint4*)g_nf;
    const int n4 = NTASK*NBINS/4;
    uint4 z = make_uint4(0u,0u,0u,0u);
    for (int j = i; j < n4; j += stride) { nb4[j]=z; nf4[j]=z; }
    if (blockIdx.x == 0) {
        if (threadIdx.x < NTASK*7) g_stat[threadIdx.x]=0.f;
        if (threadIdx.x < BB*3)    g_batch[threadIdx.x]=0.f;
        if (threadIdx.x < NTASK)   g_seedfg[threadIdx.x]=0.f;
    }
}

// Westphal peer reduction: after call, the group leader (lowest lane in peers)
// holds the group sum of v[0..5].
__device__ __forceinline__ void peerReduce6(float v[6], unsigned peers, int lane) {
    unsigned rel   = __popc(peers & ((1u<<lane)-1u));
    unsigned above = peers & ~((2u<<lane)-1u);   // lanes strictly greater (lane=31 -> 0)
    while (__any_sync(FULLM, above)) {
        int nxt = __ffs(above);                  // 1..32, 0 if none
        int src = nxt ? nxt-1 : lane;
        #pragma unroll
        for (int s = 0; s < 6; s++) {
            float t = __shfl_sync(FULLM, v[s], src);
            if (above) v[s] += t;
        }
        unsigned pa = __shfl_sync(FULLM, above, src);
        above = above ? pa : 0u;
        if (rel & 1u) above = 0u;                // odd ranks retire after donating
        rel >>= 1;
    }
}

// ---------------- stage A: per-pixel transforms + per-(b,id) stats ----------------
__global__ __launch_bounds__(256) void stageA(const float* __restrict__ pred,
                                              const int*  __restrict__ inst,
                                              const int*  __restrict__ lab) {
    __shared__ float s_acc[52];   // 7 ids * 7 stats + cls, vcnt, seedbg
    int b = blockIdx.y;
    if (threadIdx.x < 52) s_acc[threadIdx.x] = 0.f;
    __syncthreads();

    const float* pb = pred + b*(CC*HW);
    int base = blockIdx.x*1024;
    int lane = threadIdx.x & 31;
    float cls = 0.f, vc = 0.f, sbg = 0.f;

    #pragma unroll
    for (int k = 0; k < 4; k++) {
        int pix = base + k*256 + threadIdx.x;
        float p0 = pb[pix],      p1 = pb[HW+pix],   p2 = pb[2*HW+pix];
        float p3 = pb[3*HW+pix], p4 = pb[4*HW+pix];
        float p5 = pb[5*HW+pix], p6 = pb[6*HW+pix];
        int iv = inst[b*HW+pix];
        int lv = lab [b*HW+pix];
        int w = pix & (WW-1);
        int h = pix >> 10;

        float xw = (2.0f/2047.0f)*(float)w;
        float yh = (1.0f/1023.0f)*(float)h;
        float t0 = __expf(2.f*p0);
        float t1 = __expf(2.f*p1);
        float ex = __fdividef(t0-1.f, t0+1.f) + xw;   // tanh(p0)+xw
        float ey = __fdividef(t1-1.f, t1+1.f) + yh;
        float sd = __fdividef(1.f, 1.f + __expf(-p4));
        float4 P; P.x = ex; P.y = ey; P.z = sd; P.w = __int_as_float(iv);
        g_pack[b*HW+pix] = P;

        if (lv < 2) {
            float m   = fmaxf(p5, p6);
            float lse = m + __logf(__expf(p5-m) + __expf(p6-m));
            float logpt = ((lv == 0) ? p5 : p6) - lse;
            float pt  = __expf(logpt);
            float om  = 1.0f - pt;
            cls -= om*om*logpt;
            vc  += 1.0f;
        }
        if (lv == 0) sbg += sd*sd;

        // per-(id) stats via warp peer reduction (no per-pixel same-address atomics)
        float v[6] = {xw, yh, p2, p3, p2*p2, p3*p3};
        unsigned peers = __match_any_sync(FULLM, iv);
        peerReduce6(v, peers, lane);
        bool leader = (lane == __ffs(peers)-1);
        if (leader && iv >= 1) {
            float* a = &s_acc[(iv-1)*7];
            atomicAdd(a+0, (float)__popc(peers));
            atomicAdd(a+1, v[0]);
            atomicAdd(a+2, v[1]);
            atomicAdd(a+3, v[2]);
            atomicAdd(a+4, v[3]);
            atomicAdd(a+5, v[4]);
            atomicAdd(a+6, v[5]);
        }
    }
    // warp-reduce scalars, lane0 -> shared
    #pragma unroll
    for (int o = 16; o; o >>= 1) {
        cls += __shfl_down_sync(FULLM, cls, o);
        vc  += __shfl_down_sync(FULLM, vc,  o);
        sbg += __shfl_down_sync(FULLM, sbg, o);
    }
    if (lane == 0) {
        atomicAdd(&s_acc[49], cls);
        atomicAdd(&s_acc[50], vc);
        atomicAdd(&s_acc[51], sbg);
    }
    __syncthreads();
    if      (threadIdx.x < 49) atomicAdd(&g_stat[b*49 + threadIdx.x], s_acc[threadIdx.x]);
    else if (threadIdx.x < 52) atomicAdd(&g_batch[b*3 + threadIdx.x - 49], s_acc[threadIdx.x]);
}

// ---------------- stage B: per-task derived params ----------------
__global__ void stageB() {
    int t = threadIdx.x;
    if (t >= NTASK) return;
    const float* s = &g_stat[t*7];
    float cnt  = s[0];
    float pres = (cnt > 0.f) ? 1.f : 0.f;
    float cf   = fmaxf(cnt, 1.f);
    float cx = s[1]/cf, cy = s[2]/cf;
    float m0 = s[3]/cf, m1 = s[4]/cf;
    float varl = (s[5] - cnt*m0*m0 + s[6] - cnt*m1*m1) / (2.f*cf);
    g_task[t*8+0] = cx;
    g_task[t*8+1] = cy;
    g_task[t*8+2] = expf(10.f*m0);
    g_task[t*8+3] = expf(10.f*m1);
    g_task[t*8+4] = varl;
    g_task[t*8+5] = pres;
}

// ---------------- stage C: all 7 ids per block, histograms + seed_fg ----------------
__global__ __launch_bounds__(256) void stageC() {
    int b = blockIdx.y;
    __shared__ float sp[NID][5];   // cx, cy, sex, sey, present
    if (threadIdx.x < NID*5) {
        int i = threadIdx.x / 5, s = threadIdx.x % 5;
        sp[i][s] = g_task[(b*NID+i)*8 + (s < 4 ? s : 5)];
    }
    __syncthreads();

    int base = blockIdx.x*1024;
    int lane = threadIdx.x & 31;
    float sfg[NID] = {0.f,0.f,0.f,0.f,0.f,0.f,0.f};

    #pragma unroll
    for (int k = 0; k < 4; k++) {
        int pix = base + k*256 + threadIdx.x;
        float4 P = g_pack[b*HW+pix];
        int iv = __float_as_int(P.w);
        #pragma unroll
        for (int i = 0; i < NID; i++) {
            if (sp[i][4] == 0.f) continue;   // absent id: uniform skip
            float dx = P.x - sp[i][0], dy = P.y - sp[i][1];
            float d  = __expf(-(dx*dx*sp[i][2] + dy*dy*sp[i][3]));
            bool fg = (iv == i+1);
            float e = fg ? 2.f*(1.f-d) : 2.f*d;
            int bin = min((int)(e * BINSCALE), NBINS-1);
            unsigned key = ((unsigned)bin << 1) | (fg ? 1u : 0u);
            unsigned same = __match_any_sync(FULLM, key);
            if (lane == (unsigned)__ffs(same)-1) {
                unsigned* dst = (fg ? g_nf : g_nb) + (b*NID+i)*NBINS + bin;
                atomicAdd(dst, (unsigned)__popc(same));
            }
            if (fg) { float df = P.z - d; sfg[i] += df*df; }
        }
    }
    // reduce sfg[7] across block
    __shared__ float sred[NID][8];
    #pragma unroll
    for (int i = 0; i < NID; i++) {
        float s = sfg[i];
        #pragma unroll
        for (int o = 16; o; o >>= 1) s += __shfl_down_sync(FULLM, s, o);
        if (lane == 0) sred[i][threadIdx.x >> 5] = s;
    }
    __syncthreads();
    if (threadIdx.x < NID) {
        float s = 0.f;
        #pragma unroll
        for (int w = 0; w < 8; w++) s += sred[threadIdx.x][w];
        atomicAdd(&g_seedfg[b*NID + threadIdx.x], s);
    }
}

// ---------------- stage D: Lovász via descending-bin scan (fp32) ----------------
__global__ __launch_bounds__(1024) void stageD() {
    int t = blockIdx.x;
    if (g_task[t*8+5] == 0.f) { if (threadIdx.x == 0) g_instl[t] = 0.f; return; }
    const unsigned* nb = &g_nb[t*NBINS];
    const unsigned* nf = &g_nf[t*NBINS];
    int tid = threadIdx.x;
    const int BPT = NBINS/1024;   // 64 bins/thread, contiguous descending chunk
    int hi = NBINS-1 - tid*BPT;

    // pass 1: chunk sums
    unsigned lf = 0, lt = 0;
    #pragma unroll 8
    for (int j = 0; j < BPT; j++) {
        int bin = hi - j;
        unsigned a = nf[bin];
        lf += a; lt += a + nb[bin];
    }

    // block exclusive scan of (lf, lt)
    __shared__ unsigned sWF[32], sWT[32];
    int lane = tid & 31, warp = tid >> 5;
    unsigned incF = lf, incT = lt;
    #pragma unroll
    for (int o = 1; o < 32; o <<= 1) {
        unsigned vF = __shfl_up_sync(FULLM, incF, o);
        unsigned vT = __shfl_up_sync(FULLM, incT, o);
        if (lane >= o) { incF += vF; incT += vT; }
    }
    if (lane == 31) { sWF[warp] = incF; sWT[warp] = incT; }
    __syncthreads();
    if (warp == 0) {
        unsigned aF = sWF[lane], aT = sWT[lane];
        #pragma unroll
        for (int o = 1; o < 32; o <<= 1) {
            unsigned vF = __shfl_up_sync(FULLM, aF, o);
            unsigned vT = __shfl_up_sync(FULLM, aT, o);
            if (lane >= o) { aF += vF; aT += vT; }
        }
        sWF[lane] = aF; sWT[lane] = aT;
    }
    __syncthreads();
    unsigned F = (warp ? sWF[warp-1] : 0u) + incF - lf;
    unsigned T = (warp ? sWT[warp-1] : 0u) + incT - lt;

    float G = (float)sWF[31];     // exact (< 2^24)
    // jac(F,T) = 1 - (G-F)/(G+T-F); monotone. fp32 is safe: errors couple to
    // Delta-e ~ 3e-5 after summation-by-parts.
    float jprev = 1.f - (G - (float)F) / (G + (float)(T - F));
    float loss = 0.f;
    #pragma unroll 4
    for (int j = 0; j < BPT; j++) {
        int bin = hi - j;
        unsigned a = nf[bin], c = a + nb[bin];
        if (c) {
            F += a; T += c;
            float jnew = 1.f - (G - (float)F) / (G + (float)(T - F));
            float e = ((float)bin + 0.5f) * (1.0f/BINSCALE);
            loss += e * (jnew - jprev);
            jprev = jnew;
        }
    }
    // block reduce loss
    #pragma unroll
    for (int o = 16; o; o >>= 1) loss += __shfl_down_sync(FULLM, loss, o);
    __shared__ float sL[32];
    if (lane == 0) sL[warp] = loss;
    __syncthreads();
    if (warp == 0) {
        float v = sL[lane];
        #pragma unroll
        for (int o = 16; o; o >>= 1) v += __shfl_down_sync(FULLM, v, o);
        if (lane == 0) g_instl[t] = v;
    }
}

// ---------------- final combine ----------------
__global__ void combineK(float* __restrict__ out) {
    if (threadIdx.x != 0) return;
    float total = 0.f;
    for (int b = 0; b < BB; b++) {
        float ps = 0.f, il = 0.f, vl = 0.f, sf = 0.f;
        for (int i = 0; i < NID; i++) {
            int t = b*NID + i;
            float p = g_task[t*8+5];
            ps += p;
            il += g_instl[t]    * p;
            vl += g_task[t*8+4] * p;
            sf += g_seedfg[t]   * p;
        }
        float obj = fmaxf(ps, 1.f);
        float seed_loss = (g_batch[b*3+2] + 200.f*sf) / (float)HW;
        float loss_b = il/obj + 10.f*(vl/obj) + seed_loss;
        float cls_b  = g_batch[b*3+0] / fmaxf(g_batch[b*3+1], 1.f);
        total += loss_b + cls_b;
    }
    out[0] = total * 0.25f;
}

extern "C" void kernel_launch(void* const* d_in, const int* in_sizes, int n_in,
                              void* d_out, int out_size) {
    const float* pred = (const float*)d_in[0];
    const int*   inst = (const int*)  d_in[1];
    const int*   lab  = (const int*)  d_in[2];
    float* out = (float*)d_out;

    zeroK   <<<1024, 256>>>();
    stageA  <<<dim3(HW/1024, BB), 256>>>(pred, inst, lab);
    stageB  <<<1, 32>>>();
    stageC  <<<dim3(HW/1024, BB), 256>>>();
    stageD  <<<NTASK, 1024>>>();
    combineK<<<1, 32>>>(out);
}

// round 5
// speedup vs baseline: 5.1013x; 1.4051x over previous
#include <cuda_runtime.h>
#include <math.h>

#define BB 4
#define CC 7
#define HH 512
#define WW 1024
#define HW (HH*WW)            // 524288
#define NID 7
#define NTASK (BB*NID)        // 28
#define NBINS 16384           // bins over e in [0,2]; e*8192 per unit
#define FULLM 0xffffffffu

// ---- persistent scratch ----
__device__ float4   g_pack[BB*HW];          // ex, ey, seed, inst(bits)
__device__ unsigned g_hist[NTASK*NBINS*2];  // [task][bin][bg=0/fg=1]
__device__ float    g_stat[NTASK*7];        // cnt, sum_xw, sum_yh, s0, s1, s0^2, s1^2
__device__ float    g_batch[BB*3];          // cls_sum, valid_cnt, seed_bg
__device__ float    g_task[NTASK*8];        // cx, cy, sex, sey, varl, present
__device__ float    g_seedfg[NTASK];
__device__ float    g_instl[NTASK];

// ---------------- zero accumulators ----------------
__global__ __launch_bounds__(256) void zeroK() {
    int i = blockIdx.x*blockDim.x + threadIdx.x;
    int stride = gridDim.x*blockDim.x;
    uint4* h4 = (uint4*)g_hist;
    const int n4 = NTASK*NBINS*2/4;
    uint4 z = make_uint4(0u,0u,0u,0u);
    for (int j = i; j < n4; j += stride) h4[j] = z;
    if (blockIdx.x == 0) {
        if (threadIdx.x < NTASK*7) g_stat[threadIdx.x]=0.f;
        if (threadIdx.x < BB*3)    g_batch[threadIdx.x]=0.f;
        if (threadIdx.x < NTASK)   g_seedfg[threadIdx.x]=0.f;
    }
}

// ---------------- stage A: per-pixel transforms + per-(b,id) stats ----------------
// 256 threads, 8 pixels/thread. Per-warp shared slabs for id stats (<=8-way conflicts).
__global__ __launch_bounds__(256) void stageA(const float* __restrict__ pred,
                                              const int*  __restrict__ inst,
                                              const int*  __restrict__ lab) {
    __shared__ float s_slab[8][56];   // [warp][id*7+stat], 49 used + 3 scalars + pad
    int b = blockIdx.y;
    int tid = threadIdx.x;
    int lane = tid & 31, warp = tid >> 5;
    #pragma unroll
    for (int j = tid; j < 8*56; j += 256) ((float*)s_slab)[j] = 0.f;
    __syncthreads();

    const float* pb = pred + b*(CC*HW);
    int base = blockIdx.x*2048;
    float cls = 0.f, vc = 0.f, sbg = 0.f;

    #pragma unroll
    for (int k = 0; k < 8; k++) {
        int pix = base + k*256 + tid;
        float p0 = pb[pix],      p1 = pb[HW+pix],   p2 = pb[2*HW+pix];
        float p3 = pb[3*HW+pix], p4 = pb[4*HW+pix];
        float p5 = pb[5*HW+pix], p6 = pb[6*HW+pix];
        int iv = inst[b*HW+pix];
        int lv = lab [b*HW+pix];
        int w = pix & (WW-1);
        int h = pix >> 10;

        float xw = (2.0f/2047.0f)*(float)w;
        float yh = (1.0f/1023.0f)*(float)h;
        float t0 = __expf(2.f*p0);
        float t1 = __expf(2.f*p1);
        float ex = __fdividef(t0-1.f, t0+1.f) + xw;   // tanh(p0)+xw
        float ey = __fdividef(t1-1.f, t1+1.f) + yh;
        float sd = __fdividef(1.f, 1.f + __expf(-p4));
        float4 P; P.x = ex; P.y = ey; P.z = sd; P.w = __int_as_float(iv);
        g_pack[b*HW+pix] = P;

        if (lv < 2) {
            float m   = fmaxf(p5, p6);
            float lse = m + __logf(__expf(p5-m) + __expf(p6-m));
            float logpt = ((lv == 0) ? p5 : p6) - lse;
            float pt  = __expf(logpt);
            float om  = 1.0f - pt;
            cls -= om*om*logpt;
            vc  += 1.0f;
        }
        if (lv == 0) sbg += sd*sd;

        if (iv >= 1) {
            float* a = &s_slab[warp][(iv-1)*7];
            atomicAdd(a+0, 1.0f);
            atomicAdd(a+1, xw);
            atomicAdd(a+2, yh);
            atomicAdd(a+3, p2);
            atomicAdd(a+4, p3);
            atomicAdd(a+5, p2*p2);
            atomicAdd(a+6, p3*p3);
        }
    }
    // warp-reduce scalars, lane0 -> slab
    #pragma unroll
    for (int o = 16; o; o >>= 1) {
        cls += __shfl_down_sync(FULLM, cls, o);
        vc  += __shfl_down_sync(FULLM, vc,  o);
        sbg += __shfl_down_sync(FULLM, sbg, o);
    }
    if (lane == 0) { s_slab[warp][49]=cls; s_slab[warp][50]=vc; s_slab[warp][51]=sbg; }
    __syncthreads();
    if (tid < 52) {
        float s = 0.f;
        #pragma unroll
        for (int wq = 0; wq < 8; wq++) s += s_slab[wq][tid];
        if (tid < 49) atomicAdd(&g_stat[b*49 + tid], s);
        else          atomicAdd(&g_batch[b*3 + tid - 49], s);
    }
}

// ---------------- stage B: per-task derived params ----------------
__global__ void stageB() {
    int t = threadIdx.x;
    if (t >= NTASK) return;
    const float* s = &g_stat[t*7];
    float cnt  = s[0];
    float pres = (cnt > 0.f) ? 1.f : 0.f;
    float cf   = fmaxf(cnt, 1.f);
    float cx = s[1]/cf, cy = s[2]/cf;
    float m0 = s[3]/cf, m1 = s[4]/cf;
    float varl = (s[5] - cnt*m0*m0 + s[6] - cnt*m1*m1) / (2.f*cf);
    g_task[t*8+0] = cx;
    g_task[t*8+1] = cy;
    g_task[t*8+2] = expf(10.f*m0);
    g_task[t*8+3] = expf(10.f*m1);
    g_task[t*8+4] = varl;
    g_task[t*8+5] = pres;
}

// ---------------- stage C: all 7 ids per block, straight REDs ----------------
__global__ __launch_bounds__(256) void stageC() {
    int b = blockIdx.y;
    __shared__ float4 sparam[NID];
    if (threadIdx.x < NID) {
        const float* tk = &g_task[(b*NID+threadIdx.x)*8];
        sparam[threadIdx.x] = make_float4(tk[0], tk[1], tk[2], tk[3]);
    }
    __syncthreads();
    float cx[NID], cy[NID], sx[NID], sy[NID];
    #pragma unroll
    for (int i = 0; i < NID; i++) {
        float4 q = sparam[i];
        cx[i]=q.x; cy[i]=q.y; sx[i]=q.z; sy[i]=q.w;
    }
    unsigned* hb = g_hist + b*NID*NBINS*2;
    float sfg[NID] = {0.f,0.f,0.f,0.f,0.f,0.f,0.f};
    const float4* pk = g_pack + b*HW + blockIdx.x*2048 + threadIdx.x;

    #pragma unroll
    for (int k = 0; k < 8; k++) {
        float4 P = pk[k*256];
        int iv = __float_as_int(P.w);
        #pragma unroll
        for (int i = 0; i < NID; i++) {
            float dx = P.x - cx[i], dy = P.y - cy[i];
            float q  = dx*dx*sx[i] + dy*dy*sy[i];
            float d  = __expf(-q);
            bool fg  = (iv == i+1);
            float u  = d * (float)NBINS;                 // e*8192 for bg = 16384*d
            float val = fg ? (float)NBINS - u : u;       // fg: 16384*(1-d)
            int bin = min((int)val, NBINS-1);
            atomicAdd(hb + i*(NBINS*2) + bin*2 + (fg?1:0), 1u);
            float df = P.z - d;
            sfg[i] += fg ? df*df : 0.f;
        }
    }
    // reduce sfg[7] across block
    __shared__ float sred[NID][8];
    int lane = threadIdx.x & 31;
    #pragma unroll
    for (int i = 0; i < NID; i++) {
        float s = sfg[i];
        #pragma unroll
        for (int o = 16; o; o >>= 1) s += __shfl_down_sync(FULLM, s, o);
        if (lane == 0) sred[i][threadIdx.x >> 5] = s;
    }
    __syncthreads();
    if (threadIdx.x < NID) {
        float s = 0.f;
        #pragma unroll
        for (int w = 0; w < 8; w++) s += sred[threadIdx.x][w];
        atomicAdd(&g_seedfg[b*NID + threadIdx.x], s);
    }
}

// ---------------- stage D: Lovász via descending-bin scan (fp32) ----------------
__global__ __launch_bounds__(256) void stageD() {
    int t = blockIdx.x;
    if (g_task[t*8+5] == 0.f) { if (threadIdx.x == 0) g_instl[t] = 0.f; return; }
    const uint2* hh = (const uint2*)(g_hist + t*(NBINS*2));   // .x=bg .y=fg
    int tid = threadIdx.x;
    const int BPT = NBINS/256;    // 64 bins/thread, contiguous descending chunk
    int hi = NBINS-1 - tid*BPT;

    // pass 1: chunk sums
    unsigned lf = 0, lt = 0;
    #pragma unroll 8
    for (int j = 0; j < BPT; j++) {
        uint2 c = hh[hi - j];
        lf += c.y; lt += c.x + c.y;
    }

    // block exclusive scan of (lf, lt): 8 warps
    __shared__ unsigned sWF[8], sWT[8];
    int lane = tid & 31, warp = tid >> 5;
    unsigned incF = lf, incT = lt;
    #pragma unroll
    for (int o = 1; o < 32; o <<= 1) {
        unsigned vF = __shfl_up_sync(FULLM, incF, o);
        unsigned vT = __shfl_up_sync(FULLM, incT, o);
        if (lane >= o) { incF += vF; incT += vT; }
    }
    if (lane == 31) { sWF[warp] = incF; sWT[warp] = incT; }
    __syncthreads();
    if (warp == 0 && lane < 8) {
        unsigned aF = sWF[lane], aT = sWT[lane];
        #pragma unroll
        for (int o = 1; o < 8; o <<= 1) {
            unsigned vF = __shfl_up_sync(0xffu, aF, o);
            unsigned vT = __shfl_up_sync(0xffu, aT, o);
            if (lane >= o) { aF += vF; aT += vT; }
        }
        sWF[lane] = aF; sWT[lane] = aT;
    }
    __syncthreads();
    unsigned F = (warp ? sWF[warp-1] : 0u) + incF - lf;
    unsigned T = (warp ? sWT[warp-1] : 0u) + incT - lt;

    float G = (float)sWF[7];      // exact fg total (< 2^24)
    float jprev = 1.f - (G - (float)F) / (G + (float)(T - F));
    float loss = 0.f;
    #pragma unroll 4
    for (int j = 0; j < BPT; j++) {
        int bin = hi - j;
        uint2 cc = hh[bin];
        unsigned a = cc.y, c = cc.x + cc.y;
        if (c) {
            F += a; T += c;
            float jnew = 1.f - (G - (float)F) / (G + (float)(T - F));
            float e = ((float)bin + 0.5f) * (2.0f/(float)NBINS);
            loss += e * (jnew - jprev);
            jprev = jnew;
        }
    }
    // block reduce loss
    #pragma unroll
    for (int o = 16; o; o >>= 1) loss += __shfl_down_sync(FULLM, loss, o);
    __shared__ float sL[8];
    if (lane == 0) sL[warp] = loss;
    __syncthreads();
    if (tid == 0) {
        float v = 0.f;
        #pragma unroll
        for (int w = 0; w < 8; w++) v += sL[w];
        g_instl[t] = v;
    }
}

// ---------------- final combine ----------------
__global__ void combineK(float* __restrict__ out) {
    if (threadIdx.x != 0) return;
    float total = 0.f;
    for (int b = 0; b < BB; b++) {
        float ps = 0.f, il = 0.f, vl = 0.f, sf = 0.f;
        for (int i = 0; i < NID; i++) {
            int t = b*NID + i;
            float p = g_task[t*8+5];
            ps += p;
            il += g_instl[t]    * p;
            vl += g_task[t*8+4] * p;
            sf += g_seedfg[t]   * p;
        }
        float obj = fmaxf(ps, 1.f);
        float seed_loss = (g_batch[b*3+2] + 200.f*sf) / (float)HW;
        float loss_b = il/obj + 10.f*(vl/obj) + seed_loss;
        float cls_b  = g_batch[b*3+0] / fmaxf(g_batch[b*3+1], 1.f);
        total += loss_b + cls_b;
    }
    out[0] = total * 0.25f;
}

extern "C" void kernel_launch(void* const* d_in, const int* in_sizes, int n_in,
                              void* d_out, int out_size) {
    const float* pred = (const float*)d_in[0];
    const int*   inst = (const int*)  d_in[1];
    const int*   lab  = (const int*)  d_in[2];
    float* out = (float*)d_out;

    zeroK   <<<512, 256>>>();
    stageA  <<<dim3(HW/2048, BB), 256>>>(pred, inst, lab);
    stageB  <<<1, 32>>>();
    stageC  <<<dim3(HW/2048, BB), 256>>>();
    stageD  <<<NTASK, 256>>>();
    combineK<<<1, 32>>>(out);
}